// round 1
// baseline (speedup 1.0000x reference)
#include <cuda_runtime.h>

// Problem constants
#define NPIX   131072     // 8*128*128
#define CDIM   256
#define HDS    8          // heads
#define HD     32         // head dim
#define IMG    128        // H = W = 128

// Scratch (allocation-free rule: device globals)
__device__ float g_v[33554432];   // v  = x@Wv^T + bv   [B,H,W,C]
__device__ float g_o[33554432];   // o  = aggregation    [B,H,W,C]

// ---------------------------------------------------------------------------
// SGEMM: C[M,256] = A[M,256] @ W[256,256]^T + bias   (both operands K-major)
// Block tile 128x128, BK=16, 256 threads, 8x8 register micro-tile.
// ---------------------------------------------------------------------------
#define BM 128
#define BN 128
#define BK 16
#define TM 8
#define TN 8

__global__ void gemm_bias_kernel(const float* __restrict__ A,
                                 const float* __restrict__ W,
                                 const float* __restrict__ bias,
                                 float* __restrict__ C)
{
    __shared__ float As[BK][BM];
    __shared__ float Bs[BK][BN];

    const int K   = CDIM;
    const int bm  = blockIdx.x * BM;
    const int bn  = blockIdx.y * BN;
    const int tid = threadIdx.x;

    // global->smem load mapping: 2 float4 per thread per operand per k-tile
    const int lr = tid >> 2;          // 0..63
    const int lc = (tid & 3) << 2;    // 0,4,8,12

    // compute mapping
    const int tr = (tid >> 4) << 3;   // 0..120
    const int tc = (tid & 15) << 3;   // 0..120

    float acc[TM][TN];
#pragma unroll
    for (int m = 0; m < TM; m++)
#pragma unroll
        for (int n = 0; n < TN; n++) acc[m][n] = 0.f;

    for (int k0 = 0; k0 < K; k0 += BK) {
#pragma unroll
        for (int s = 0; s < 2; s++) {
            const int r = lr + s * 64;
            float4 a = *reinterpret_cast<const float4*>(A + (size_t)(bm + r) * K + k0 + lc);
            As[lc + 0][r] = a.x; As[lc + 1][r] = a.y;
            As[lc + 2][r] = a.z; As[lc + 3][r] = a.w;
            float4 w = *reinterpret_cast<const float4*>(W + (size_t)(bn + r) * K + k0 + lc);
            Bs[lc + 0][r] = w.x; Bs[lc + 1][r] = w.y;
            Bs[lc + 2][r] = w.z; Bs[lc + 3][r] = w.w;
        }
        __syncthreads();

#pragma unroll
        for (int kk = 0; kk < BK; kk++) {
            float af[TM], bf[TN];
#pragma unroll
            for (int m = 0; m < TM; m += 4)
                *reinterpret_cast<float4*>(&af[m]) =
                    *reinterpret_cast<const float4*>(&As[kk][tr + m]);
#pragma unroll
            for (int n = 0; n < TN; n += 4)
                *reinterpret_cast<float4*>(&bf[n]) =
                    *reinterpret_cast<const float4*>(&Bs[kk][tc + n]);
#pragma unroll
            for (int m = 0; m < TM; m++)
#pragma unroll
                for (int n = 0; n < TN; n++)
                    acc[m][n] += af[m] * bf[n];
        }
        __syncthreads();
    }

    float bcol[TN];
#pragma unroll
    for (int n = 0; n < TN; n++) bcol[n] = bias[bn + tc + n];

#pragma unroll
    for (int m = 0; m < TM; m++) {
        const size_t row = (size_t)(bm + tr + m) * CDIM + bn + tc;
        float4 o0, o1;
        o0.x = acc[m][0] + bcol[0]; o0.y = acc[m][1] + bcol[1];
        o0.z = acc[m][2] + bcol[2]; o0.w = acc[m][3] + bcol[3];
        o1.x = acc[m][4] + bcol[4]; o1.y = acc[m][5] + bcol[5];
        o1.z = acc[m][6] + bcol[6]; o1.w = acc[m][7] + bcol[7];
        *reinterpret_cast<float4*>(C + row)     = o0;
        *reinterpret_cast<float4*>(C + row + 4) = o1;
    }
}

// ---------------------------------------------------------------------------
// Neighborhood aggregation (NAT 7x7, clipped windows).
// One CTA = (batch b, head h, 16x16 spatial tile).
// Halo v tile (<=22x22 x 32 fp32) staged in dynamic smem; lane = head-dim d,
// attn weights are warp-uniform broadcasts from gmem (L1-cached).
// out[b,h,i,j,d] = sum_{ki,kj} attn[b,h,i,j,ki*7+kj] * v[b,h, si+ki, sj+kj, d]
//   with si = clip(i-3, 0, 121), sj = clip(j-3, 0, 121).
// ---------------------------------------------------------------------------
#define AGTILE 16
#define HALO   22

__global__ void agg_kernel(const float* __restrict__ v,
                           const float* __restrict__ attn,
                           float* __restrict__ o)
{
    const int tile = blockIdx.x;   // 0..63
    const int head = blockIdx.y;   // 0..7
    const int b    = blockIdx.z;   // 0..7
    const int i0 = (tile >> 3) * AGTILE;
    const int j0 = (tile & 7)  * AGTILE;

    // union of clipped windows for this tile
    const int rs = min(max(i0 - 3, 0), IMG - 7);
    const int cs = min(max(j0 - 3, 0), IMG - 7);
    const int re = min(max(i0 + AGTILE - 4, 0), IMG - 7) + 6;
    const int ce = min(max(j0 + AGTILE - 4, 0), IMG - 7) + 6;
    const int nr = re - rs + 1;    // <= 22
    const int nc = ce - cs + 1;    // <= 22

    extern __shared__ float vs[];  // [HALO][HALO][HD], row stride HALO*HD

    const int tid = threadIdx.x;

    // cooperative halo load, float4-vectorized over head-dim
    const float* vbase = v + (size_t)b * IMG * IMG * CDIM + head * HD;
    const int nquads = nr * nc * (HD / 4);
    for (int idx = tid; idx < nquads; idx += 256) {
        const int d4 = idx & 7;
        const int p  = idx >> 3;
        const int r  = p / nc;
        const int c  = p - r * nc;
        float4 val = *reinterpret_cast<const float4*>(
            vbase + ((size_t)(rs + r) * IMG + (cs + c)) * CDIM + d4 * 4);
        *reinterpret_cast<float4*>(vs + (r * HALO + c) * HD + d4 * 4) = val;
    }
    __syncthreads();

    const int warp = tid >> 5;
    const int lane = tid & 31;

    for (int s = 0; s < 32; s++) {
        const int p  = warp * 32 + s;          // pixel within tile
        const int ti = p >> 4, tj = p & 15;
        const int i = i0 + ti, j = j0 + tj;
        const int si = min(max(i - 3, 0), IMG - 7) - rs;
        const int sj = min(max(j - 3, 0), IMG - 7) - cs;

        const float* ap = attn + ((((size_t)b * HDS + head) * IMG + i) * IMG + j) * 49;
        const float* vp = vs + (si * HALO + sj) * HD + lane;

        float acc = 0.f;
#pragma unroll
        for (int ki = 0; ki < 7; ki++) {
#pragma unroll
            for (int kj = 0; kj < 7; kj++) {
                acc += __ldg(ap + ki * 7 + kj) * vp[(ki * HALO + kj) * HD];
            }
        }
        o[(((size_t)b * IMG + i) * IMG + j) * CDIM + head * HD + lane] = acc;
    }
}

// ---------------------------------------------------------------------------
extern "C" void kernel_launch(void* const* d_in, const int* in_sizes, int n_in,
                              void* d_out, int out_size)
{
    const float* x    = (const float*)d_in[0];
    const float* attn = (const float*)d_in[1];
    const float* Wv   = (const float*)d_in[2];
    const float* bv   = (const float*)d_in[3];
    const float* Wp   = (const float*)d_in[4];
    const float* bp   = (const float*)d_in[5];
    float*       out  = (float*)d_out;

    void* pv = nullptr;
    void* po = nullptr;
    cudaGetSymbolAddress(&pv, g_v);
    cudaGetSymbolAddress(&po, g_o);
    float* vbuf = (float*)pv;
    float* obuf = (float*)po;

    const int agg_smem = HALO * HALO * HD * (int)sizeof(float);  // 61952
    cudaFuncSetAttribute(agg_kernel,
                         cudaFuncAttributeMaxDynamicSharedMemorySize, agg_smem);

    dim3 ggrid(NPIX / BM, CDIM / BN);   // (1024, 2)
    gemm_bias_kernel<<<ggrid, 256>>>(x, Wv, bv, vbuf);

    dim3 agrid(64, HDS, 8);             // tiles, heads, batch
    agg_kernel<<<agrid, 256, agg_smem>>>(vbuf, attn, obuf);

    gemm_bias_kernel<<<ggrid, 256>>>(obuf, Wp, bp, out);
}

// round 3
// speedup vs baseline: 1.8353x; 1.8353x over previous
#include <cuda_runtime.h>
#include <cuda_bf16.h>
#include <cstdint>

#define IMG   128
#define CDIM  256
#define HDS   8
#define HD    32
#define NELEM 33554432   // 131072 * 256

// Scratch (allocation-free rule: device globals)
__device__ float          g_v[NELEM];      // v buffer fp32
__device__ __nv_bfloat16  g_xh[NELEM], g_xl[NELEM];   // x split
__device__ __nv_bfloat16  g_oh[NELEM], g_ol[NELEM];   // agg output split
__device__ __nv_bfloat16  g_wvh[65536], g_wvl[65536];
__device__ __nv_bfloat16  g_wph[65536], g_wpl[65536];

// ---------------------------------------------------------------------------
// helpers
// ---------------------------------------------------------------------------
__device__ __forceinline__ uint32_t smem_u32(const void* p) {
    uint32_t a;
    asm("{ .reg .u64 t; cvta.to.shared.u64 t, %1; cvt.u32.u64 %0, t; }"
        : "=r"(a) : "l"(p));
    return a;
}
__device__ __forceinline__ void cp16(uint32_t saddr, const void* g) {
    asm volatile("cp.async.cg.shared.global [%0], [%1], 16;"
                 :: "r"(saddr), "l"(g));
}
__device__ __forceinline__ void ldm_x4(uint32_t* d, uint32_t a) {
    asm volatile("ldmatrix.sync.aligned.m8n8.x4.shared.b16 {%0,%1,%2,%3}, [%4];"
                 : "=r"(d[0]), "=r"(d[1]), "=r"(d[2]), "=r"(d[3]) : "r"(a));
}
__device__ __forceinline__ void ldm_x2(uint32_t* d, uint32_t a) {
    asm volatile("ldmatrix.sync.aligned.m8n8.x2.shared.b16 {%0,%1}, [%2];"
                 : "=r"(d[0]), "=r"(d[1]) : "r"(a));
}
__device__ __forceinline__ void mma16816(float* c, const uint32_t* a, const uint32_t* b) {
    asm volatile("mma.sync.aligned.m16n8k16.row.col.f32.bf16.bf16.f32 "
                 "{%0,%1,%2,%3}, {%4,%5,%6,%7}, {%8,%9}, {%0,%1,%2,%3};"
                 : "+f"(c[0]), "+f"(c[1]), "+f"(c[2]), "+f"(c[3])
                 : "r"(a[0]), "r"(a[1]), "r"(a[2]), "r"(a[3]),
                   "r"(b[0]), "r"(b[1]));
}
__device__ __forceinline__ uint32_t pack_bf2(float x, float y) {
    __nv_bfloat162 t = __floats2bfloat162_rn(x, y);
    return *reinterpret_cast<uint32_t*>(&t);
}

// ---------------------------------------------------------------------------
// W split: fp32 -> bf16 hi/lo (both weight matrices)
// ---------------------------------------------------------------------------
__global__ void split_w_kernel(const float* __restrict__ W1,
                               __nv_bfloat16* __restrict__ h1, __nv_bfloat16* __restrict__ l1,
                               const float* __restrict__ W2,
                               __nv_bfloat16* __restrict__ h2, __nv_bfloat16* __restrict__ l2)
{
    int i = blockIdx.x * 256 + threadIdx.x;
    float a = W1[i];
    __nv_bfloat16 ha = __float2bfloat16(a);
    h1[i] = ha;
    l1[i] = __float2bfloat16(a - __bfloat162float(ha));
    float b = W2[i];
    __nv_bfloat16 hb = __float2bfloat16(b);
    h2[i] = hb;
    l2[i] = __float2bfloat16(b - __bfloat162float(hb));
}

// ---------------------------------------------------------------------------
// x split: fp32 -> bf16 hi/lo, float4 per thread
// ---------------------------------------------------------------------------
__global__ void convert_x_kernel(const float* __restrict__ x,
                                 __nv_bfloat16* __restrict__ h,
                                 __nv_bfloat16* __restrict__ l)
{
    const size_t i = ((size_t)blockIdx.x * 256 + threadIdx.x) * 4;
    float4 a = *reinterpret_cast<const float4*>(x + i);
    __nv_bfloat16 h0 = __float2bfloat16(a.x), h1 = __float2bfloat16(a.y);
    __nv_bfloat16 h2 = __float2bfloat16(a.z), h3 = __float2bfloat16(a.w);
    uint2 hp, lp;
    hp.x = ((uint32_t)__bfloat16_as_ushort(h1) << 16) | __bfloat16_as_ushort(h0);
    hp.y = ((uint32_t)__bfloat16_as_ushort(h3) << 16) | __bfloat16_as_ushort(h2);
    lp.x = pack_bf2(a.x - __bfloat162float(h0), a.y - __bfloat162float(h1));
    lp.y = pack_bf2(a.z - __bfloat162float(h2), a.w - __bfloat162float(h3));
    *reinterpret_cast<uint2*>(h + i) = hp;
    *reinterpret_cast<uint2*>(l + i) = lp;
}

// ---------------------------------------------------------------------------
// bf16x3 mma.sync GEMM: C[M,256] = A @ W^T + bias
//   CTA tile 128x128, 256 threads, 8 warps (4M x 2N), warp tile 32x64.
//   K chunks of 32, 2-stage cp.async double buffer.
//   smem rows padded to 40 bf16 (80B).
// ---------------------------------------------------------------------------
#define ST_BYTES 40960          // 4 matrices * 128 rows * 80B
#define OFF_AH 0
#define OFF_AL 10240
#define OFF_BH 20480
#define OFF_BL 30720
#define GM_SMEM (2 * ST_BYTES)  // 81920

__global__ void __launch_bounds__(256, 2)
gemm_tc_kernel(const __nv_bfloat16* __restrict__ Ah_g,
               const __nv_bfloat16* __restrict__ Al_g,
               const __nv_bfloat16* __restrict__ Bh_g,
               const __nv_bfloat16* __restrict__ Bl_g,
               const float* __restrict__ bias,
               float* __restrict__ C)
{
    extern __shared__ char sm[];
    const uint32_t sb  = smem_u32(sm);
    const int tid  = threadIdx.x;
    const int wid  = tid >> 5, lane = tid & 31;
    const int bm   = blockIdx.x * 128;
    const int bn   = blockIdx.y * 128;
    const int m0   = (wid & 3) * 32;     // warp M offset
    const int n0   = (wid >> 2) * 64;    // warp N offset

    // per-chunk loader: 2 x (4 cp16) per thread
    auto load_chunk = [&](int kc, int st) {
#pragma unroll
        for (int s = 0; s < 2; s++) {
            const int idx = tid + s * 256;      // 0..511
            const int r = idx >> 2, c = idx & 3;
            const uint32_t so = (uint32_t)(st * ST_BYTES + r * 80 + c * 16);
            const size_t goA = (size_t)(bm + r) * 256 + kc * 32 + c * 8;
            const size_t goB = (size_t)(bn + r) * 256 + kc * 32 + c * 8;
            cp16(sb + so + OFF_AH, Ah_g + goA);
            cp16(sb + so + OFF_AL, Al_g + goA);
            cp16(sb + so + OFF_BH, Bh_g + goB);
            cp16(sb + so + OFF_BL, Bl_g + goB);
        }
    };

    float acc[2][8][4];
#pragma unroll
    for (int mt = 0; mt < 2; mt++)
#pragma unroll
        for (int nt = 0; nt < 8; nt++)
#pragma unroll
            for (int r = 0; r < 4; r++) acc[mt][nt][r] = 0.f;

    load_chunk(0, 0);
    asm volatile("cp.async.commit_group;" ::: "memory");

    // lane-local ldmatrix address components
    const int a_row = (lane & 15);
    const int a_kof = (lane >> 4) << 3;
    const int b_row = (lane & 7);
    const int b_kof = ((lane >> 3) & 1) << 3;

    for (int kc = 0; kc < 8; kc++) {
        if (kc < 7) {
            load_chunk(kc + 1, (kc + 1) & 1);
            asm volatile("cp.async.commit_group;" ::: "memory");
            asm volatile("cp.async.wait_group 1;" ::: "memory");
        } else {
            asm volatile("cp.async.wait_group 0;" ::: "memory");
        }
        __syncthreads();

        const uint32_t stb = sb + (uint32_t)((kc & 1) * ST_BYTES);
#pragma unroll
        for (int k16 = 0; k16 < 2; k16++) {
            const int kk = k16 * 16;
            uint32_t AhF[2][4], AlF[2][4];
#pragma unroll
            for (int mt = 0; mt < 2; mt++) {
                const uint32_t aaddr = stb + (uint32_t)((m0 + mt * 16 + a_row) * 80
                                                        + (kk + a_kof) * 2);
                ldm_x4(AhF[mt], aaddr + OFF_AH);
                ldm_x4(AlF[mt], aaddr + OFF_AL);
            }
#pragma unroll
            for (int nt = 0; nt < 8; nt++) {
                const uint32_t baddr = stb + (uint32_t)((n0 + nt * 8 + b_row) * 80
                                                        + (kk + b_kof) * 2);
                uint32_t bf[2];
                ldm_x2(bf, baddr + OFF_BH);
                mma16816(acc[0][nt], AhF[0], bf);
                mma16816(acc[1][nt], AhF[1], bf);
                mma16816(acc[0][nt], AlF[0], bf);
                mma16816(acc[1][nt], AlF[1], bf);
                ldm_x2(bf, baddr + OFF_BL);
                mma16816(acc[0][nt], AhF[0], bf);
                mma16816(acc[1][nt], AhF[1], bf);
            }
        }
        __syncthreads();
    }

    // epilogue: c-frag lane layout: rows lane>>2 (+8), cols 2*(lane&3)
#pragma unroll
    for (int mt = 0; mt < 2; mt++) {
        const int row = bm + m0 + mt * 16 + (lane >> 2);
#pragma unroll
        for (int nt = 0; nt < 8; nt++) {
            const int col = bn + n0 + nt * 8 + 2 * (lane & 3);
            const float b0 = __ldg(bias + col), b1 = __ldg(bias + col + 1);
            float2 v0, v1;
            v0.x = acc[mt][nt][0] + b0; v0.y = acc[mt][nt][1] + b1;
            v1.x = acc[mt][nt][2] + b0; v1.y = acc[mt][nt][3] + b1;
            *reinterpret_cast<float2*>(C + (size_t)row * 256 + col) = v0;
            *reinterpret_cast<float2*>(C + (size_t)(row + 8) * 256 + col) = v1;
        }
    }
}

// ---------------------------------------------------------------------------
// Neighborhood aggregation (NAT 7x7, clipped).
// Weights staged in smem padded to 52 floats/pixel, loaded as 13 LDS.128 into
// registers. Output written directly as bf16 hi/lo for GEMM2.
// ---------------------------------------------------------------------------
#define AGTILE 16
#define HALO   22
#define WPAD   52
#define VS_FLOATS (HALO * HALO * HD)            // 15488
#define AGG_SMEM  ((VS_FLOATS + 256 * WPAD) * 4)  // 115200

__global__ void agg_kernel(const float* __restrict__ v,
                           const float* __restrict__ attn,
                           __nv_bfloat16* __restrict__ oh,
                           __nv_bfloat16* __restrict__ ol)
{
    const int tile = blockIdx.x;
    const int head = blockIdx.y;
    const int b    = blockIdx.z;
    const int i0 = (tile >> 3) * AGTILE;
    const int j0 = (tile & 7)  * AGTILE;

    const int rs = min(max(i0 - 3, 0), IMG - 7);
    const int cs = min(max(j0 - 3, 0), IMG - 7);
    const int re = min(max(i0 + AGTILE - 4, 0), IMG - 7) + 6;
    const int ce = min(max(j0 + AGTILE - 4, 0), IMG - 7) + 6;
    const int nr = re - rs + 1;
    const int nc = ce - cs + 1;

    extern __shared__ float sm_f[];
    float* vs = sm_f;
    float* ws = sm_f + VS_FLOATS;

    const int tid = threadIdx.x;

    // halo v tile load (float4 over head-dim)
    const float* vbase = v + (size_t)b * IMG * IMG * CDIM + head * HD;
    const int nquads = nr * nc * (HD / 4);
    for (int idx = tid; idx < nquads; idx += 256) {
        const int d4 = idx & 7;
        const int p  = idx >> 3;
        const int r  = p / nc;
        const int c  = p - r * nc;
        float4 val = *reinterpret_cast<const float4*>(
            vbase + ((size_t)(rs + r) * IMG + (cs + c)) * CDIM + d4 * 4);
        *reinterpret_cast<float4*>(vs + (r * HALO + c) * HD + d4 * 4) = val;
    }

    // attn weights -> smem, padded to WPAD per pixel
    const float* abase = attn + ((((size_t)b * HDS + head) * IMG + i0) * IMG + j0) * 49;
    for (int idx = tid; idx < 256 * 49; idx += 256) {
        const int p = idx / 49;
        const int k = idx - p * 49;
        ws[p * WPAD + k] = __ldg(abase + ((size_t)(p >> 4) * IMG + (p & 15)) * 49 + k);
    }
    __syncthreads();

    const int warp = tid >> 5;
    const int lane = tid & 31;

    for (int s = 0; s < 32; s++) {
        const int p  = warp * 32 + s;
        const int ti = p >> 4, tj = p & 15;
        const int i = i0 + ti, j = j0 + tj;
        const int si = min(max(i - 3, 0), IMG - 7) - rs;
        const int sj = min(max(j - 3, 0), IMG - 7) - cs;

        // weights into registers: 13 LDS.128
        float w[52];
        const float4* wq = reinterpret_cast<const float4*>(ws + p * WPAD);
#pragma unroll
        for (int q = 0; q < 13; q++)
            *reinterpret_cast<float4*>(&w[q * 4]) = wq[q];

        const float* vp = vs + (si * HALO + sj) * HD + lane;
        float acc = 0.f;
#pragma unroll
        for (int ki = 0; ki < 7; ki++) {
#pragma unroll
            for (int kj = 0; kj < 7; kj++) {
                acc += w[ki * 7 + kj] * vp[(ki * HALO + kj) * HD];
            }
        }
        const size_t oidx = (((size_t)b * IMG + i) * IMG + j) * CDIM + head * HD + lane;
        __nv_bfloat16 hi = __float2bfloat16(acc);
        oh[oidx] = hi;
        ol[oidx] = __float2bfloat16(acc - __bfloat162float(hi));
    }
}

// ---------------------------------------------------------------------------
extern "C" void kernel_launch(void* const* d_in, const int* in_sizes, int n_in,
                              void* d_out, int out_size)
{
    const float* x    = (const float*)d_in[0];
    const float* attn = (const float*)d_in[1];
    const float* Wv   = (const float*)d_in[2];
    const float* bv   = (const float*)d_in[3];
    const float* Wp   = (const float*)d_in[4];
    const float* bp   = (const float*)d_in[5];
    float*       out  = (float*)d_out;

    void *pv, *pxh, *pxl, *poh, *pol, *pwvh, *pwvl, *pwph, *pwpl;
    cudaGetSymbolAddress(&pv,   g_v);
    cudaGetSymbolAddress(&pxh,  g_xh);
    cudaGetSymbolAddress(&pxl,  g_xl);
    cudaGetSymbolAddress(&poh,  g_oh);
    cudaGetSymbolAddress(&pol,  g_ol);
    cudaGetSymbolAddress(&pwvh, g_wvh);
    cudaGetSymbolAddress(&pwvl, g_wvl);
    cudaGetSymbolAddress(&pwph, g_wph);
    cudaGetSymbolAddress(&pwpl, g_wpl);

    cudaFuncSetAttribute(gemm_tc_kernel,
                         cudaFuncAttributeMaxDynamicSharedMemorySize, GM_SMEM);
    cudaFuncSetAttribute(agg_kernel,
                         cudaFuncAttributeMaxDynamicSharedMemorySize, AGG_SMEM);

    split_w_kernel<<<256, 256>>>(Wv, (__nv_bfloat16*)pwvh, (__nv_bfloat16*)pwvl,
                                 Wp, (__nv_bfloat16*)pwph, (__nv_bfloat16*)pwpl);
    convert_x_kernel<<<32768, 256>>>(x, (__nv_bfloat16*)pxh, (__nv_bfloat16*)pxl);

    dim3 ggrid(1024, 2);
    gemm_tc_kernel<<<ggrid, 256, GM_SMEM>>>((__nv_bfloat16*)pxh, (__nv_bfloat16*)pxl,
                                            (__nv_bfloat16*)pwvh, (__nv_bfloat16*)pwvl,
                                            bv, (float*)pv);

    dim3 agrid(64, HDS, 8);
    agg_kernel<<<agrid, 256, AGG_SMEM>>>((float*)pv, attn,
                                         (__nv_bfloat16*)poh, (__nv_bfloat16*)pol);

    gemm_tc_kernel<<<ggrid, 256, GM_SMEM>>>((__nv_bfloat16*)poh, (__nv_bfloat16*)pol,
                                            (__nv_bfloat16*)pwph, (__nv_bfloat16*)pwpl,
                                            bp, out);
}

// round 4
// speedup vs baseline: 2.0829x; 1.1349x over previous
#include <cuda_runtime.h>
#include <cuda_bf16.h>
#include <cstdint>

#define IMG   128
#define CDIM  256
#define HDS   8
#define HD    32
#define NELEM 33554432   // 131072 * 256

// Scratch (allocation-free rule: device globals)
__device__ float          g_v[NELEM];      // v buffer fp32
__device__ __nv_bfloat16  g_xh[NELEM], g_xl[NELEM];   // x split
__device__ __nv_bfloat16  g_oh[NELEM], g_ol[NELEM];   // agg output split
__device__ __nv_bfloat16  g_wvh[65536], g_wvl[65536];
__device__ __nv_bfloat16  g_wph[65536], g_wpl[65536];

// ---------------------------------------------------------------------------
// helpers
// ---------------------------------------------------------------------------
__device__ __forceinline__ uint32_t smem_u32(const void* p) {
    uint32_t a;
    asm("{ .reg .u64 t; cvta.to.shared.u64 t, %1; cvt.u32.u64 %0, t; }"
        : "=r"(a) : "l"(p));
    return a;
}
__device__ __forceinline__ void cp16(uint32_t saddr, const void* g) {
    asm volatile("cp.async.cg.shared.global [%0], [%1], 16;"
                 :: "r"(saddr), "l"(g));
}
__device__ __forceinline__ void ldm_x4(uint32_t* d, uint32_t a) {
    asm volatile("ldmatrix.sync.aligned.m8n8.x4.shared.b16 {%0,%1,%2,%3}, [%4];"
                 : "=r"(d[0]), "=r"(d[1]), "=r"(d[2]), "=r"(d[3]) : "r"(a));
}
__device__ __forceinline__ void ldm_x2(uint32_t* d, uint32_t a) {
    asm volatile("ldmatrix.sync.aligned.m8n8.x2.shared.b16 {%0,%1}, [%2];"
                 : "=r"(d[0]), "=r"(d[1]) : "r"(a));
}
__device__ __forceinline__ void mma16816(float* c, const uint32_t* a, const uint32_t* b) {
    asm volatile("mma.sync.aligned.m16n8k16.row.col.f32.bf16.bf16.f32 "
                 "{%0,%1,%2,%3}, {%4,%5,%6,%7}, {%8,%9}, {%0,%1,%2,%3};"
                 : "+f"(c[0]), "+f"(c[1]), "+f"(c[2]), "+f"(c[3])
                 : "r"(a[0]), "r"(a[1]), "r"(a[2]), "r"(a[3]),
                   "r"(b[0]), "r"(b[1]));
}
__device__ __forceinline__ uint32_t pack_bf2(float x, float y) {
    __nv_bfloat162 t = __floats2bfloat162_rn(x, y);
    return *reinterpret_cast<uint32_t*>(&t);
}

// ---------------------------------------------------------------------------
// W split: fp32 -> bf16 hi/lo (both weight matrices)
// ---------------------------------------------------------------------------
__global__ void split_w_kernel(const float* __restrict__ W1,
                               __nv_bfloat16* __restrict__ h1, __nv_bfloat16* __restrict__ l1,
                               const float* __restrict__ W2,
                               __nv_bfloat16* __restrict__ h2, __nv_bfloat16* __restrict__ l2)
{
    int i = blockIdx.x * 256 + threadIdx.x;
    float a = W1[i];
    __nv_bfloat16 ha = __float2bfloat16(a);
    h1[i] = ha;
    l1[i] = __float2bfloat16(a - __bfloat162float(ha));
    float b = W2[i];
    __nv_bfloat16 hb = __float2bfloat16(b);
    h2[i] = hb;
    l2[i] = __float2bfloat16(b - __bfloat162float(hb));
}

// ---------------------------------------------------------------------------
// x split: fp32 -> bf16 hi/lo, float4 per thread
// ---------------------------------------------------------------------------
__global__ void convert_x_kernel(const float* __restrict__ x,
                                 __nv_bfloat16* __restrict__ h,
                                 __nv_bfloat16* __restrict__ l)
{
    const size_t i = ((size_t)blockIdx.x * 256 + threadIdx.x) * 4;
    float4 a = *reinterpret_cast<const float4*>(x + i);
    __nv_bfloat16 h0 = __float2bfloat16(a.x), h1 = __float2bfloat16(a.y);
    __nv_bfloat16 h2 = __float2bfloat16(a.z), h3 = __float2bfloat16(a.w);
    uint2 hp, lp;
    hp.x = ((uint32_t)__bfloat16_as_ushort(h1) << 16) | __bfloat16_as_ushort(h0);
    hp.y = ((uint32_t)__bfloat16_as_ushort(h3) << 16) | __bfloat16_as_ushort(h2);
    lp.x = pack_bf2(a.x - __bfloat162float(h0), a.y - __bfloat162float(h1));
    lp.y = pack_bf2(a.z - __bfloat162float(h2), a.w - __bfloat162float(h3));
    *reinterpret_cast<uint2*>(h + i) = hp;
    *reinterpret_cast<uint2*>(l + i) = lp;
}

// ---------------------------------------------------------------------------
// bf16x3 mma.sync GEMM (unchanged from R3): C[M,256] = A @ W^T + bias
// ---------------------------------------------------------------------------
#define ST_BYTES 40960
#define OFF_AH 0
#define OFF_AL 10240
#define OFF_BH 20480
#define OFF_BL 30720
#define GM_SMEM (2 * ST_BYTES)

__global__ void __launch_bounds__(256, 2)
gemm_tc_kernel(const __nv_bfloat16* __restrict__ Ah_g,
               const __nv_bfloat16* __restrict__ Al_g,
               const __nv_bfloat16* __restrict__ Bh_g,
               const __nv_bfloat16* __restrict__ Bl_g,
               const float* __restrict__ bias,
               float* __restrict__ C)
{
    extern __shared__ char sm[];
    const uint32_t sb  = smem_u32(sm);
    const int tid  = threadIdx.x;
    const int wid  = tid >> 5, lane = tid & 31;
    const int bm   = blockIdx.x * 128;
    const int bn   = blockIdx.y * 128;
    const int m0   = (wid & 3) * 32;
    const int n0   = (wid >> 2) * 64;

    auto load_chunk = [&](int kc, int st) {
#pragma unroll
        for (int s = 0; s < 2; s++) {
            const int idx = tid + s * 256;
            const int r = idx >> 2, c = idx & 3;
            const uint32_t so = (uint32_t)(st * ST_BYTES + r * 80 + c * 16);
            const size_t goA = (size_t)(bm + r) * 256 + kc * 32 + c * 8;
            const size_t goB = (size_t)(bn + r) * 256 + kc * 32 + c * 8;
            cp16(sb + so + OFF_AH, Ah_g + goA);
            cp16(sb + so + OFF_AL, Al_g + goA);
            cp16(sb + so + OFF_BH, Bh_g + goB);
            cp16(sb + so + OFF_BL, Bl_g + goB);
        }
    };

    float acc[2][8][4];
#pragma unroll
    for (int mt = 0; mt < 2; mt++)
#pragma unroll
        for (int nt = 0; nt < 8; nt++)
#pragma unroll
            for (int r = 0; r < 4; r++) acc[mt][nt][r] = 0.f;

    load_chunk(0, 0);
    asm volatile("cp.async.commit_group;" ::: "memory");

    const int a_row = (lane & 15);
    const int a_kof = (lane >> 4) << 3;
    const int b_row = (lane & 7);
    const int b_kof = ((lane >> 3) & 1) << 3;

    for (int kc = 0; kc < 8; kc++) {
        if (kc < 7) {
            load_chunk(kc + 1, (kc + 1) & 1);
            asm volatile("cp.async.commit_group;" ::: "memory");
            asm volatile("cp.async.wait_group 1;" ::: "memory");
        } else {
            asm volatile("cp.async.wait_group 0;" ::: "memory");
        }
        __syncthreads();

        const uint32_t stb = sb + (uint32_t)((kc & 1) * ST_BYTES);
#pragma unroll
        for (int k16 = 0; k16 < 2; k16++) {
            const int kk = k16 * 16;
            uint32_t AhF[2][4], AlF[2][4];
#pragma unroll
            for (int mt = 0; mt < 2; mt++) {
                const uint32_t aaddr = stb + (uint32_t)((m0 + mt * 16 + a_row) * 80
                                                        + (kk + a_kof) * 2);
                ldm_x4(AhF[mt], aaddr + OFF_AH);
                ldm_x4(AlF[mt], aaddr + OFF_AL);
            }
#pragma unroll
            for (int nt = 0; nt < 8; nt++) {
                const uint32_t baddr = stb + (uint32_t)((n0 + nt * 8 + b_row) * 80
                                                        + (kk + b_kof) * 2);
                uint32_t bf[2];
                ldm_x2(bf, baddr + OFF_BH);
                mma16816(acc[0][nt], AhF[0], bf);
                mma16816(acc[1][nt], AhF[1], bf);
                mma16816(acc[0][nt], AlF[0], bf);
                mma16816(acc[1][nt], AlF[1], bf);
                ldm_x2(bf, baddr + OFF_BL);
                mma16816(acc[0][nt], AhF[0], bf);
                mma16816(acc[1][nt], AhF[1], bf);
            }
        }
        __syncthreads();
    }

#pragma unroll
    for (int mt = 0; mt < 2; mt++) {
        const int row = bm + m0 + mt * 16 + (lane >> 2);
#pragma unroll
        for (int nt = 0; nt < 8; nt++) {
            const int col = bn + n0 + nt * 8 + 2 * (lane & 3);
            const float b0 = __ldg(bias + col), b1 = __ldg(bias + col + 1);
            float2 v0, v1;
            v0.x = acc[mt][nt][0] + b0; v0.y = acc[mt][nt][1] + b1;
            v1.x = acc[mt][nt][2] + b0; v1.y = acc[mt][nt][3] + b1;
            *reinterpret_cast<float2*>(C + (size_t)row * 256 + col) = v0;
            *reinterpret_cast<float2*>(C + (size_t)(row + 8) * 256 + col) = v1;
        }
    }
}

// ---------------------------------------------------------------------------
// Neighborhood aggregation with register-rolling 7x7 window.
// CLS 0: left border tile (j0==0), 1: interior, 2: right border (j0==112).
// Shift schedule is compile-time per class -> static register rotation.
// ---------------------------------------------------------------------------
#define AGTILE 16
#define HALO   22
#define WPAD   52
#define VS_FLOATS (HALO * HALO * HD)              // 15488
#define AGG_SMEM  ((VS_FLOATS + 256 * WPAD) * 4)  // 115200

__device__ __forceinline__ constexpr int shifts_fn(int CLS, int tj) {
    return CLS == 0 ? (tj > 3 ? tj - 3 : 0)
         : CLS == 1 ? tj
         : (tj < 12 ? tj : 12);
}

template <int CLS>
__device__ __forceinline__ void agg_body(
    const float* __restrict__ vs, const float* __restrict__ ws,
    int i0, int j0, int rs,
    int warp, int lane, int b, int head,
    __nv_bfloat16* __restrict__ oh, __nv_bfloat16* __restrict__ ol)
{
#pragma unroll
    for (int rr = 0; rr < 2; rr++) {
        const int ti = warp * 2 + rr;
        const int i  = i0 + ti;
        const int si = min(max(i - 3, 0), IMG - 7) - rs;
        const float* vrow = vs + si * (HALO * HD) + lane;

        float v[7][7];
#pragma unroll
        for (int ki = 0; ki < 7; ki++)
#pragma unroll
            for (int kj = 0; kj < 7; kj++)
                v[ki][kj] = vrow[(ki * HALO + kj) * HD];

#pragma unroll
        for (int tj = 0; tj < AGTILE; tj++) {
            const int sh = shifts_fn(CLS, tj);
            if (tj > 0 && sh != shifts_fn(CLS, tj - 1)) {
                const int c = sh + 6;
                const int slot = c % 7;
#pragma unroll
                for (int ki = 0; ki < 7; ki++)
                    v[ki][slot] = vrow[(ki * HALO + c) * HD];
            }

            const int p = ti * AGTILE + tj;
            const float4* wq = reinterpret_cast<const float4*>(ws + p * WPAD);
            float a0 = 0.f, a1 = 0.f, a2 = 0.f, a3 = 0.f;
#pragma unroll
            for (int q = 0; q < 13; q++) {
                const float4 wv = wq[q];
#pragma unroll
                for (int e = 0; e < 4; e++) {
                    const int idx = q * 4 + e;
                    if (idx < 49) {
                        const int ki = idx / 7, kj = idx % 7;
                        const float we = (e == 0) ? wv.x : (e == 1) ? wv.y
                                       : (e == 2) ? wv.z : wv.w;
                        const float vv = v[ki][(sh + kj) % 7];
                        if (e == 0)      a0 += we * vv;
                        else if (e == 1) a1 += we * vv;
                        else if (e == 2) a2 += we * vv;
                        else             a3 += we * vv;
                    }
                }
            }
            const float acc = (a0 + a1) + (a2 + a3);

            const int j = j0 + tj;
            const size_t oidx = (((size_t)b * IMG + i) * IMG + j) * CDIM
                              + head * HD + lane;
            __nv_bfloat16 hi = __float2bfloat16(acc);
            oh[oidx] = hi;
            ol[oidx] = __float2bfloat16(acc - __bfloat162float(hi));
        }
    }
}

__global__ void __launch_bounds__(256, 2)
agg_kernel(const float* __restrict__ v,
           const float* __restrict__ attn,
           __nv_bfloat16* __restrict__ oh,
           __nv_bfloat16* __restrict__ ol)
{
    const int tile = blockIdx.x;
    const int head = blockIdx.y;
    const int b    = blockIdx.z;
    const int i0 = (tile >> 3) * AGTILE;
    const int j0 = (tile & 7)  * AGTILE;

    const int rs = min(max(i0 - 3, 0), IMG - 7);
    const int cs = min(max(j0 - 3, 0), IMG - 7);
    const int re = min(max(i0 + AGTILE - 4, 0), IMG - 7) + 6;
    const int ce = min(max(j0 + AGTILE - 4, 0), IMG - 7) + 6;
    const int nr = re - rs + 1;
    const int nc = ce - cs + 1;

    extern __shared__ float sm_f[];
    float* vs = sm_f;
    float* ws = sm_f + VS_FLOATS;

    const int tid = threadIdx.x;

    // halo v tile load (float4 over head-dim)
    const float* vbase = v + (size_t)b * IMG * IMG * CDIM + head * HD;
    const int nquads = nr * nc * (HD / 4);
    for (int idx = tid; idx < nquads; idx += 256) {
        const int d4 = idx & 7;
        const int p  = idx >> 3;
        const int r  = p / nc;
        const int c  = p - r * nc;
        float4 val = *reinterpret_cast<const float4*>(
            vbase + ((size_t)(rs + r) * IMG + (cs + c)) * CDIM + d4 * 4);
        *reinterpret_cast<float4*>(vs + (r * HALO + c) * HD + d4 * 4) = val;
    }

    // attn weights -> smem, padded to WPAD per pixel
    const float* abase = attn + ((((size_t)b * HDS + head) * IMG + i0) * IMG + j0) * 49;
    for (int idx = tid; idx < 256 * 49; idx += 256) {
        const int p = idx / 49;
        const int k = idx - p * 49;
        ws[p * WPAD + k] = __ldg(abase + ((size_t)(p >> 4) * IMG + (p & 15)) * 49 + k);
    }
    __syncthreads();

    const int warp = tid >> 5;
    const int lane = tid & 31;

    if (j0 == 0)
        agg_body<0>(vs, ws, i0, j0, rs, warp, lane, b, head, oh, ol);
    else if (j0 == IMG - AGTILE)
        agg_body<2>(vs, ws, i0, j0, rs, warp, lane, b, head, oh, ol);
    else
        agg_body<1>(vs, ws, i0, j0, rs, warp, lane, b, head, oh, ol);
}

// ---------------------------------------------------------------------------
extern "C" void kernel_launch(void* const* d_in, const int* in_sizes, int n_in,
                              void* d_out, int out_size)
{
    const float* x    = (const float*)d_in[0];
    const float* attn = (const float*)d_in[1];
    const float* Wv   = (const float*)d_in[2];
    const float* bv   = (const float*)d_in[3];
    const float* Wp   = (const float*)d_in[4];
    const float* bp   = (const float*)d_in[5];
    float*       out  = (float*)d_out;

    void *pv, *pxh, *pxl, *poh, *pol, *pwvh, *pwvl, *pwph, *pwpl;
    cudaGetSymbolAddress(&pv,   g_v);
    cudaGetSymbolAddress(&pxh,  g_xh);
    cudaGetSymbolAddress(&pxl,  g_xl);
    cudaGetSymbolAddress(&poh,  g_oh);
    cudaGetSymbolAddress(&pol,  g_ol);
    cudaGetSymbolAddress(&pwvh, g_wvh);
    cudaGetSymbolAddress(&pwvl, g_wvl);
    cudaGetSymbolAddress(&pwph, g_wph);
    cudaGetSymbolAddress(&pwpl, g_wpl);

    cudaFuncSetAttribute(gemm_tc_kernel,
                         cudaFuncAttributeMaxDynamicSharedMemorySize, GM_SMEM);
    cudaFuncSetAttribute(agg_kernel,
                         cudaFuncAttributeMaxDynamicSharedMemorySize, AGG_SMEM);

    split_w_kernel<<<256, 256>>>(Wv, (__nv_bfloat16*)pwvh, (__nv_bfloat16*)pwvl,
                                 Wp, (__nv_bfloat16*)pwph, (__nv_bfloat16*)pwpl);
    convert_x_kernel<<<32768, 256>>>(x, (__nv_bfloat16*)pxh, (__nv_bfloat16*)pxl);

    dim3 ggrid(1024, 2);
    gemm_tc_kernel<<<ggrid, 256, GM_SMEM>>>((__nv_bfloat16*)pxh, (__nv_bfloat16*)pxl,
                                            (__nv_bfloat16*)pwvh, (__nv_bfloat16*)pwvl,
                                            bv, (float*)pv);

    dim3 agrid(64, HDS, 8);
    agg_kernel<<<agrid, 256, AGG_SMEM>>>((float*)pv, attn,
                                         (__nv_bfloat16*)poh, (__nv_bfloat16*)pol);

    gemm_tc_kernel<<<ggrid, 256, GM_SMEM>>>((__nv_bfloat16*)poh, (__nv_bfloat16*)pol,
                                            (__nv_bfloat16*)pwph, (__nv_bfloat16*)pwpl,
                                            bp, out);
}

// round 5
// speedup vs baseline: 2.2062x; 1.0592x over previous
#include <cuda_runtime.h>
#include <cuda_bf16.h>
#include <cstdint>

#define IMG   128
#define CDIM  256
#define HDS   8
#define HD    32
#define NELEM 33554432   // 131072 * 256

// Scratch (allocation-free rule: device globals)
__device__ float          g_v[NELEM];                 // v buffer fp32
__device__ __nv_bfloat16  g_oh[NELEM], g_ol[NELEM];   // agg output split
__device__ __nv_bfloat16  g_wvh[65536], g_wvl[65536];
__device__ __nv_bfloat16  g_wph[65536], g_wpl[65536];

// ---------------------------------------------------------------------------
// helpers
// ---------------------------------------------------------------------------
__device__ __forceinline__ uint32_t smem_u32(const void* p) {
    uint32_t a;
    asm("{ .reg .u64 t; cvta.to.shared.u64 t, %1; cvt.u32.u64 %0, t; }"
        : "=r"(a) : "l"(p));
    return a;
}
__device__ __forceinline__ void cp16(uint32_t saddr, const void* g) {
    asm volatile("cp.async.cg.shared.global [%0], [%1], 16;"
                 :: "r"(saddr), "l"(g));
}
__device__ __forceinline__ void ldm_x4(uint32_t* d, uint32_t a) {
    asm volatile("ldmatrix.sync.aligned.m8n8.x4.shared.b16 {%0,%1,%2,%3}, [%4];"
                 : "=r"(d[0]), "=r"(d[1]), "=r"(d[2]), "=r"(d[3]) : "r"(a));
}
__device__ __forceinline__ void ldm_x2(uint32_t* d, uint32_t a) {
    asm volatile("ldmatrix.sync.aligned.m8n8.x2.shared.b16 {%0,%1}, [%2];"
                 : "=r"(d[0]), "=r"(d[1]) : "r"(a));
}
__device__ __forceinline__ void mma16816(float* c, const uint32_t* a, const uint32_t* b) {
    asm volatile("mma.sync.aligned.m16n8k16.row.col.f32.bf16.bf16.f32 "
                 "{%0,%1,%2,%3}, {%4,%5,%6,%7}, {%8,%9}, {%0,%1,%2,%3};"
                 : "+f"(c[0]), "+f"(c[1]), "+f"(c[2]), "+f"(c[3])
                 : "r"(a[0]), "r"(a[1]), "r"(a[2]), "r"(a[3]),
                   "r"(b[0]), "r"(b[1]));
}
__device__ __forceinline__ uint32_t pack_bf2(float x, float y) {
    __nv_bfloat162 t = __floats2bfloat162_rn(x, y);
    return *reinterpret_cast<uint32_t*>(&t);
}
__device__ __forceinline__ uint32_t pack_hi2(float x, float y) {
    __nv_bfloat16 hx = __float2bfloat16(x), hy = __float2bfloat16(y);
    return ((uint32_t)__bfloat16_as_ushort(hy) << 16) | __bfloat16_as_ushort(hx);
}
__device__ __forceinline__ uint32_t pack_lo2(float x, float y) {
    __nv_bfloat16 hx = __float2bfloat16(x), hy = __float2bfloat16(y);
    return pack_bf2(x - __bfloat162float(hx), y - __bfloat162float(hy));
}

// ---------------------------------------------------------------------------
// W split: fp32 -> bf16 hi/lo (both weight matrices)
// ---------------------------------------------------------------------------
__global__ void split_w_kernel(const float* __restrict__ W1,
                               __nv_bfloat16* __restrict__ h1, __nv_bfloat16* __restrict__ l1,
                               const float* __restrict__ W2,
                               __nv_bfloat16* __restrict__ h2, __nv_bfloat16* __restrict__ l2)
{
    int i = blockIdx.x * 256 + threadIdx.x;
    float a = W1[i];
    __nv_bfloat16 ha = __float2bfloat16(a);
    h1[i] = ha;
    l1[i] = __float2bfloat16(a - __bfloat162float(ha));
    float b = W2[i];
    __nv_bfloat16 hb = __float2bfloat16(b);
    h2[i] = hb;
    l2[i] = __float2bfloat16(b - __bfloat162float(hb));
}

// ---------------------------------------------------------------------------
// GEMM shared layout: smem rows padded to 40 bf16 (80B)
// ---------------------------------------------------------------------------
#define ST_BYTES 40960
#define OFF_AH 0
#define OFF_AL 10240
#define OFF_BH 20480
#define OFF_BL 30720
#define GM_SMEM (2 * ST_BYTES)

// Shared mainloop body used by both GEMM variants.
struct GemmCtx {
    uint32_t sb;
    int tid, wid, lane, bm, bn, m0, n0;
    int a_row, a_kof, b_row, b_kof;
};

__device__ __forceinline__ void gemm_compute_chunk(
    const GemmCtx& g, int kc, float acc[2][8][4])
{
    const uint32_t stb = g.sb + (uint32_t)((kc & 1) * ST_BYTES);
#pragma unroll
    for (int k16 = 0; k16 < 2; k16++) {
        const int kk = k16 * 16;
        uint32_t AhF[2][4], AlF[2][4];
#pragma unroll
        for (int mt = 0; mt < 2; mt++) {
            const uint32_t aaddr = stb + (uint32_t)((g.m0 + mt * 16 + g.a_row) * 80
                                                    + (kk + g.a_kof) * 2);
            ldm_x4(AhF[mt], aaddr + OFF_AH);
            ldm_x4(AlF[mt], aaddr + OFF_AL);
        }
#pragma unroll
        for (int nt = 0; nt < 8; nt++) {
            const uint32_t baddr = stb + (uint32_t)((g.n0 + nt * 8 + g.b_row) * 80
                                                    + (kk + g.b_kof) * 2);
            uint32_t bf[2];
            ldm_x2(bf, baddr + OFF_BH);
            mma16816(acc[0][nt], AhF[0], bf);
            mma16816(acc[1][nt], AhF[1], bf);
            mma16816(acc[0][nt], AlF[0], bf);
            mma16816(acc[1][nt], AlF[1], bf);
            ldm_x2(bf, baddr + OFF_BL);
            mma16816(acc[0][nt], AhF[0], bf);
            mma16816(acc[1][nt], AhF[1], bf);
        }
    }
}

__device__ __forceinline__ void gemm_epilogue(
    const GemmCtx& g, float acc[2][8][4],
    const float* __restrict__ bias, float* __restrict__ C)
{
#pragma unroll
    for (int mt = 0; mt < 2; mt++) {
        const int row = g.bm + g.m0 + mt * 16 + (g.lane >> 2);
#pragma unroll
        for (int nt = 0; nt < 8; nt++) {
            const int col = g.bn + g.n0 + nt * 8 + 2 * (g.lane & 3);
            const float b0 = __ldg(bias + col), b1 = __ldg(bias + col + 1);
            float2 v0, v1;
            v0.x = acc[mt][nt][0] + b0; v0.y = acc[mt][nt][1] + b1;
            v1.x = acc[mt][nt][2] + b0; v1.y = acc[mt][nt][3] + b1;
            *reinterpret_cast<float2*>(C + (size_t)row * 256 + col) = v0;
            *reinterpret_cast<float2*>(C + (size_t)(row + 8) * 256 + col) = v1;
        }
    }
}

__device__ __forceinline__ GemmCtx gemm_ctx_init(uint32_t sb) {
    GemmCtx g;
    g.sb = sb;
    g.tid = threadIdx.x;
    g.wid = g.tid >> 5; g.lane = g.tid & 31;
    g.bm = blockIdx.x * 128; g.bn = blockIdx.y * 128;
    g.m0 = (g.wid & 3) * 32; g.n0 = (g.wid >> 2) * 64;
    g.a_row = (g.lane & 15);
    g.a_kof = (g.lane >> 4) << 3;
    g.b_row = (g.lane & 7);
    g.b_kof = ((g.lane >> 3) & 1) << 3;
    return g;
}

// ---------------------------------------------------------------------------
// GEMM1: A fp32 (split to bf16 hi/lo inline), B bf16 hi/lo via cp.async.
// ---------------------------------------------------------------------------
__global__ void __launch_bounds__(256, 2)
gemm_f32a_kernel(const float* __restrict__ A_g,
                 const __nv_bfloat16* __restrict__ Bh_g,
                 const __nv_bfloat16* __restrict__ Bl_g,
                 const float* __restrict__ bias,
                 float* __restrict__ C)
{
    extern __shared__ char sm[];
    const uint32_t sb = smem_u32(sm);
    GemmCtx g = gemm_ctx_init(sb);
    const int tid = g.tid;

    // task mapping (same for A regs and B cp.async): idx = tid + s*256
    // r = idx>>2 (row 0..127), c = idx&3 (16B bf16 group / 32B fp32 group)
    auto ldg_a = [&](int kc, float4* r4) {
#pragma unroll
        for (int s = 0; s < 2; s++) {
            const int idx = tid + s * 256;
            const int r = idx >> 2, c = idx & 3;
            const float* p = A_g + (size_t)(g.bm + r) * 256 + kc * 32 + c * 8;
            r4[s * 2 + 0] = *reinterpret_cast<const float4*>(p);
            r4[s * 2 + 1] = *reinterpret_cast<const float4*>(p + 4);
        }
    };
    auto sts_a = [&](int st, const float4* r4) {
#pragma unroll
        for (int s = 0; s < 2; s++) {
            const int idx = tid + s * 256;
            const int r = idx >> 2, c = idx & 3;
            const uint32_t so = (uint32_t)(st * ST_BYTES + r * 80 + c * 16);
            const float4 v0 = r4[s * 2 + 0], v1 = r4[s * 2 + 1];
            uint4 hp, lp;
            hp.x = pack_hi2(v0.x, v0.y); hp.y = pack_hi2(v0.z, v0.w);
            hp.z = pack_hi2(v1.x, v1.y); hp.w = pack_hi2(v1.z, v1.w);
            lp.x = pack_lo2(v0.x, v0.y); lp.y = pack_lo2(v0.z, v0.w);
            lp.z = pack_lo2(v1.x, v1.y); lp.w = pack_lo2(v1.z, v1.w);
            *reinterpret_cast<uint4*>(sm + OFF_AH + so) = hp;
            *reinterpret_cast<uint4*>(sm + OFF_AL + so) = lp;
        }
    };
    auto cp_b = [&](int kc, int st) {
#pragma unroll
        for (int s = 0; s < 2; s++) {
            const int idx = tid + s * 256;
            const int r = idx >> 2, c = idx & 3;
            const uint32_t so = (uint32_t)(st * ST_BYTES + r * 80 + c * 16);
            const size_t go = (size_t)(g.bn + r) * 256 + kc * 32 + c * 8;
            cp16(sb + so + OFF_BH, Bh_g + go);
            cp16(sb + so + OFF_BL, Bl_g + go);
        }
    };

    float acc[2][8][4];
#pragma unroll
    for (int mt = 0; mt < 2; mt++)
#pragma unroll
        for (int nt = 0; nt < 8; nt++)
#pragma unroll
            for (int r = 0; r < 4; r++) acc[mt][nt][r] = 0.f;

    float4 areg[4];
    ldg_a(0, areg);
    cp_b(0, 0);
    asm volatile("cp.async.commit_group;" ::: "memory");

    for (int kc = 0; kc < 8; kc++) {
        sts_a(kc & 1, areg);                 // buf[kc&1] free since compute kc-2
        if (kc < 7) {
            ldg_a(kc + 1, areg);             // lands during compute(kc)
            cp_b(kc + 1, (kc + 1) & 1);
            asm volatile("cp.async.commit_group;" ::: "memory");
            asm volatile("cp.async.wait_group 1;" ::: "memory");
        } else {
            asm volatile("cp.async.wait_group 0;" ::: "memory");
        }
        __syncthreads();
        gemm_compute_chunk(g, kc, acc);
        __syncthreads();
    }
    gemm_epilogue(g, acc, bias, C);
}

// ---------------------------------------------------------------------------
// GEMM2: A bf16 hi/lo (from agg) via cp.async. (R3/R4 kernel, refactored)
// ---------------------------------------------------------------------------
__global__ void __launch_bounds__(256, 2)
gemm_bf16a_kernel(const __nv_bfloat16* __restrict__ Ah_g,
                  const __nv_bfloat16* __restrict__ Al_g,
                  const __nv_bfloat16* __restrict__ Bh_g,
                  const __nv_bfloat16* __restrict__ Bl_g,
                  const float* __restrict__ bias,
                  float* __restrict__ C)
{
    extern __shared__ char sm[];
    const uint32_t sb = smem_u32(sm);
    GemmCtx g = gemm_ctx_init(sb);
    const int tid = g.tid;

    auto load_chunk = [&](int kc, int st) {
#pragma unroll
        for (int s = 0; s < 2; s++) {
            const int idx = tid + s * 256;
            const int r = idx >> 2, c = idx & 3;
            const uint32_t so = (uint32_t)(st * ST_BYTES + r * 80 + c * 16);
            const size_t goA = (size_t)(g.bm + r) * 256 + kc * 32 + c * 8;
            const size_t goB = (size_t)(g.bn + r) * 256 + kc * 32 + c * 8;
            cp16(sb + so + OFF_AH, Ah_g + goA);
            cp16(sb + so + OFF_AL, Al_g + goA);
            cp16(sb + so + OFF_BH, Bh_g + goB);
            cp16(sb + so + OFF_BL, Bl_g + goB);
        }
    };

    float acc[2][8][4];
#pragma unroll
    for (int mt = 0; mt < 2; mt++)
#pragma unroll
        for (int nt = 0; nt < 8; nt++)
#pragma unroll
            for (int r = 0; r < 4; r++) acc[mt][nt][r] = 0.f;

    load_chunk(0, 0);
    asm volatile("cp.async.commit_group;" ::: "memory");

    for (int kc = 0; kc < 8; kc++) {
        if (kc < 7) {
            load_chunk(kc + 1, (kc + 1) & 1);
            asm volatile("cp.async.commit_group;" ::: "memory");
            asm volatile("cp.async.wait_group 1;" ::: "memory");
        } else {
            asm volatile("cp.async.wait_group 0;" ::: "memory");
        }
        __syncthreads();
        gemm_compute_chunk(g, kc, acc);
        __syncthreads();
    }
    gemm_epilogue(g, acc, bias, C);
}

// ---------------------------------------------------------------------------
// Neighborhood aggregation, register-rolling 7x7 window, TWO-PHASE weight
// staging (128 px/phase) -> smem 88576 B -> 2 CTAs/SM.
// ---------------------------------------------------------------------------
#define AGTILE 16
#define HALO   22
#define WPAD   52
#define VS_FLOATS (HALO * HALO * HD)              // 15488
#define WS_FLOATS (128 * WPAD)                    // 6656
#define AGG_SMEM  ((VS_FLOATS + WS_FLOATS) * 4)   // 88576

__device__ __forceinline__ constexpr int shifts_fn(int CLS, int tj) {
    return CLS == 0 ? (tj > 3 ? tj - 3 : 0)
         : CLS == 1 ? tj
         : (tj < 12 ? tj : 12);
}

template <int CLS>
__device__ __forceinline__ void agg_row(
    const float* __restrict__ vs, const float* __restrict__ ws,
    int i0, int j0, int rs, int ti,
    int warp, int lane, int b, int head,
    __nv_bfloat16* __restrict__ oh, __nv_bfloat16* __restrict__ ol)
{
    const int i  = i0 + ti;
    const int si = min(max(i - 3, 0), IMG - 7) - rs;
    const float* vrow = vs + si * (HALO * HD) + lane;

    float v[7][7];
#pragma unroll
    for (int ki = 0; ki < 7; ki++)
#pragma unroll
        for (int kj = 0; kj < 7; kj++)
            v[ki][kj] = vrow[(ki * HALO + kj) * HD];

#pragma unroll
    for (int tj = 0; tj < AGTILE; tj++) {
        const int sh = shifts_fn(CLS, tj);
        if (tj > 0 && sh != shifts_fn(CLS, tj - 1)) {
            const int c = sh + 6;
            const int slot = c % 7;
#pragma unroll
            for (int ki = 0; ki < 7; ki++)
                v[ki][slot] = vrow[(ki * HALO + c) * HD];
        }

        const int pl = warp * AGTILE + tj;     // local pixel in this phase
        const float4* wq = reinterpret_cast<const float4*>(ws + pl * WPAD);
        float a0 = 0.f, a1 = 0.f, a2 = 0.f, a3 = 0.f;
#pragma unroll
        for (int q = 0; q < 13; q++) {
            const float4 wv = wq[q];
#pragma unroll
            for (int e = 0; e < 4; e++) {
                const int idx = q * 4 + e;
                if (idx < 49) {
                    const int ki = idx / 7, kj = idx % 7;
                    const float we = (e == 0) ? wv.x : (e == 1) ? wv.y
                                   : (e == 2) ? wv.z : wv.w;
                    const float vv = v[ki][(sh + kj) % 7];
                    if (e == 0)      a0 += we * vv;
                    else if (e == 1) a1 += we * vv;
                    else if (e == 2) a2 += we * vv;
                    else             a3 += we * vv;
                }
            }
        }
        const float acc = (a0 + a1) + (a2 + a3);

        const int j = j0 + tj;
        const size_t oidx = (((size_t)b * IMG + i) * IMG + j) * CDIM
                          + head * HD + lane;
        __nv_bfloat16 hi = __float2bfloat16(acc);
        oh[oidx] = hi;
        ol[oidx] = __float2bfloat16(acc - __bfloat162float(hi));
    }
}

__global__ void __launch_bounds__(256, 2)
agg_kernel(const float* __restrict__ v,
           const float* __restrict__ attn,
           __nv_bfloat16* __restrict__ oh,
           __nv_bfloat16* __restrict__ ol)
{
    const int tile = blockIdx.x;
    const int head = blockIdx.y;
    const int b    = blockIdx.z;
    const int i0 = (tile >> 3) * AGTILE;
    const int j0 = (tile & 7)  * AGTILE;

    const int rs = min(max(i0 - 3, 0), IMG - 7);
    const int cs = min(max(j0 - 3, 0), IMG - 7);
    const int re = min(max(i0 + AGTILE - 4, 0), IMG - 7) + 6;
    const int ce = min(max(j0 + AGTILE - 4, 0), IMG - 7) + 6;
    const int nr = re - rs + 1;
    const int nc = ce - cs + 1;

    extern __shared__ float sm_f[];
    float* vs = sm_f;
    float* ws = sm_f + VS_FLOATS;

    const int tid = threadIdx.x;
    const int warp = tid >> 5;
    const int lane = tid & 31;

    // halo v tile load (float4 over head-dim)
    const float* vbase = v + (size_t)b * IMG * IMG * CDIM + head * HD;
    const int nquads = nr * nc * (HD / 4);
    for (int idx = tid; idx < nquads; idx += 256) {
        const int d4 = idx & 7;
        const int p  = idx >> 3;
        const int r  = p / nc;
        const int c  = p - r * nc;
        float4 val = *reinterpret_cast<const float4*>(
            vbase + ((size_t)(rs + r) * IMG + (cs + c)) * CDIM + d4 * 4);
        *reinterpret_cast<float4*>(vs + (r * HALO + c) * HD + d4 * 4) = val;
    }

    const float* abase = attn + ((((size_t)b * HDS + head) * IMG + i0) * IMG + j0) * 49;

#pragma unroll
    for (int ph = 0; ph < 2; ph++) {
        // stage weights for rows [ph*8, ph*8+8)
        for (int idx = tid; idx < 128 * 49; idx += 256) {
            const int pl = idx / 49;
            const int k  = idx - pl * 49;
            const int ti = ph * 8 + (pl >> 4);
            const int tj = pl & 15;
            ws[pl * WPAD + k] = __ldg(abase + ((size_t)ti * IMG + tj) * 49 + k);
        }
        __syncthreads();

        const int ti = ph * 8 + warp;
        if (j0 == 0)
            agg_row<0>(vs, ws, i0, j0, rs, ti, warp, lane, b, head, oh, ol);
        else if (j0 == IMG - AGTILE)
            agg_row<2>(vs, ws, i0, j0, rs, ti, warp, lane, b, head, oh, ol);
        else
            agg_row<1>(vs, ws, i0, j0, rs, ti, warp, lane, b, head, oh, ol);
        __syncthreads();
    }
}

// ---------------------------------------------------------------------------
extern "C" void kernel_launch(void* const* d_in, const int* in_sizes, int n_in,
                              void* d_out, int out_size)
{
    const float* x    = (const float*)d_in[0];
    const float* attn = (const float*)d_in[1];
    const float* Wv   = (const float*)d_in[2];
    const float* bv   = (const float*)d_in[3];
    const float* Wp   = (const float*)d_in[4];
    const float* bp   = (const float*)d_in[5];
    float*       out  = (float*)d_out;

    void *pv, *poh, *pol, *pwvh, *pwvl, *pwph, *pwpl;
    cudaGetSymbolAddress(&pv,   g_v);
    cudaGetSymbolAddress(&poh,  g_oh);
    cudaGetSymbolAddress(&pol,  g_ol);
    cudaGetSymbolAddress(&pwvh, g_wvh);
    cudaGetSymbolAddress(&pwvl, g_wvl);
    cudaGetSymbolAddress(&pwph, g_wph);
    cudaGetSymbolAddress(&pwpl, g_wpl);

    cudaFuncSetAttribute(gemm_f32a_kernel,
                         cudaFuncAttributeMaxDynamicSharedMemorySize, GM_SMEM);
    cudaFuncSetAttribute(gemm_bf16a_kernel,
                         cudaFuncAttributeMaxDynamicSharedMemorySize, GM_SMEM);
    cudaFuncSetAttribute(agg_kernel,
                         cudaFuncAttributeMaxDynamicSharedMemorySize, AGG_SMEM);

    split_w_kernel<<<256, 256>>>(Wv, (__nv_bfloat16*)pwvh, (__nv_bfloat16*)pwvl,
                                 Wp, (__nv_bfloat16*)pwph, (__nv_bfloat16*)pwpl);

    dim3 ggrid(1024, 2);
    gemm_f32a_kernel<<<ggrid, 256, GM_SMEM>>>(x,
                                              (__nv_bfloat16*)pwvh, (__nv_bfloat16*)pwvl,
                                              bv, (float*)pv);

    dim3 agrid(64, HDS, 8);
    agg_kernel<<<agrid, 256, AGG_SMEM>>>((float*)pv, attn,
                                         (__nv_bfloat16*)poh, (__nv_bfloat16*)pol);

    gemm_bf16a_kernel<<<ggrid, 256, GM_SMEM>>>((__nv_bfloat16*)poh, (__nv_bfloat16*)pol,
                                               (__nv_bfloat16*)pwph, (__nv_bfloat16*)pwpl,
                                               bp, out);
}